// round 16
// baseline (speedup 1.0000x reference)
#include <cuda_runtime.h>
#include <cuda_bf16.h>
#include <cuda_fp16.h>
#include <cstdint>

#define BATCH 2
#define SEQ   2048
#define EMB   2048
#define HQ    16
#define HKV   4
#define HD    128
#define KVW   (HKV * HD)        // 512
#define MROWS (BATCH * SEQ)     // 4096
#define QKVW  (EMB + 2 * KVW)   // 3072

// ---------------------------------------------------------------------------
// PTX helpers — ONLY non-arch-suffixed instructions (compute_103-safe)
// ---------------------------------------------------------------------------
__device__ __forceinline__ uint32_t smem_u32(const void* p) {
    uint32_t a;
    asm("{ .reg .u64 t; cvta.to.shared.u64 t, %1; cvt.u32.u64 %0, t; }"
        : "=r"(a) : "l"(p));
    return a;
}

__device__ __forceinline__ void cp16(uint32_t saddr, const void* gaddr) {
    asm volatile("cp.async.cg.shared.global [%0], [%1], 16;"
                 :: "r"(saddr), "l"(gaddr));
}

__device__ __forceinline__ void ldmx4(uint32_t* r, uint32_t addr) {
    asm volatile("ldmatrix.sync.aligned.m8n8.x4.shared.b16 {%0,%1,%2,%3}, [%4];"
                 : "=r"(r[0]), "=r"(r[1]), "=r"(r[2]), "=r"(r[3]) : "r"(addr));
}

__device__ __forceinline__ void ldmx4t(uint32_t* r, uint32_t addr) {
    asm volatile("ldmatrix.sync.aligned.m8n8.x4.trans.shared.b16 {%0,%1,%2,%3}, [%4];"
                 : "=r"(r[0]), "=r"(r[1]), "=r"(r[2]), "=r"(r[3]) : "r"(addr));
}

// fp16 mma
__device__ __forceinline__ void mma16816h(float* c, const uint32_t* a,
                                          const uint32_t* b) {
    asm volatile(
        "mma.sync.aligned.m16n8k16.row.col.f32.f16.f16.f32 "
        "{%0,%1,%2,%3}, {%4,%5,%6,%7}, {%8,%9}, {%0,%1,%2,%3};"
        : "+f"(c[0]), "+f"(c[1]), "+f"(c[2]), "+f"(c[3])
        : "r"(a[0]), "r"(a[1]), "r"(a[2]), "r"(a[3]), "r"(b[0]), "r"(b[1]));
}

__device__ __forceinline__ float ex2(float x) {
    float y;
    asm("ex2.approx.f32 %0, %1;" : "=f"(y) : "f"(x));
    return y;
}

// ---------------------------------------------------------------------------
// Device scratch (no cudaMalloc allowed)
// ---------------------------------------------------------------------------
__device__ __half g_xh[(size_t)MROWS * EMB];       // x fp16
__device__ __half g_qkv[(size_t)MROWS * QKVW];     // fused q|k|v fp16
__device__ __half g_oh[(size_t)MROWS * EMB];       // attn out fp16
__device__ __half g_wc[(size_t)QKVW * EMB];        // concat Wq|Wk|Wv ^T fp16
__device__ __half g_wo[(size_t)EMB * EMB];         // Wo^T fp16
__device__ float  g_bias[QKVW];                    // concat bq|bk|bv

// ---------------------------------------------------------------------------
// fp32 -> fp16 convert (elementwise)
// ---------------------------------------------------------------------------
__global__ __launch_bounds__(256) void to_half_kernel(
    const float* __restrict__ x, __half* __restrict__ y, int n)
{
    int i = (blockIdx.x * 256 + threadIdx.x) * 4;
    if (i >= n) return;
    float4 v = *(const float4*)(x + i);
    __half2 h0 = __floats2half2_rn(v.x, v.y);
    __half2 h1 = __floats2half2_rn(v.z, v.w);
    uint2 o = make_uint2(*(uint32_t*)&h0, *(uint32_t*)&h1);
    *(uint2*)(y + i) = o;
}

// ---------------------------------------------------------------------------
// Merged transpose of Wq|Wk|Wv into the concat fp16 buffer [QKVW, EMB],
// with the bias concat fused in (blocks at kBase==0 copy 32 bias values).
// ---------------------------------------------------------------------------
__global__ __launch_bounds__(256) void transpose_qkv_kernel(
    const float* __restrict__ Wq, const float* __restrict__ Wk,
    const float* __restrict__ Wv, __half* __restrict__ T,
    const float* __restrict__ bq, const float* __restrict__ bk,
    const float* __restrict__ bv, float* __restrict__ biasOut)
{
    __shared__ float tile[32][33];
    const int tx = threadIdx.x, ty = threadIdx.y;
    const int nBase = blockIdx.x * 32;   // 0..QKVW-32
    const int kBase = blockIdx.y * 32;   // 0..EMB-32

    const float* W;
    const float* bsrc;
    int srcN, ln;
    if (nBase < EMB)            { W = Wq; bsrc = bq; srcN = EMB; ln = nBase; }
    else if (nBase < EMB + KVW) { W = Wk; bsrc = bk; srcN = KVW; ln = nBase - EMB; }
    else                        { W = Wv; bsrc = bv; srcN = KVW; ln = nBase - EMB - KVW; }

    if (kBase == 0 && ty == 0)
        biasOut[nBase + tx] = bsrc[ln + tx];

#pragma unroll
    for (int i = 0; i < 4; i++)
        tile[ty + 8 * i][tx] = W[(size_t)(kBase + ty + 8 * i) * srcN + ln + tx];
    __syncthreads();
#pragma unroll
    for (int i = 0; i < 4; i++) {
        float v = tile[tx][ty + 8 * i];
        T[(size_t)(nBase + ty + 8 * i) * EMB + kBase + tx] = __float2half(v);
    }
}

// ---------------------------------------------------------------------------
// Transpose: W [K,N] fp32 -> T [N,K] fp16
// ---------------------------------------------------------------------------
__global__ __launch_bounds__(256) void transpose_half_kernel(
    const float* __restrict__ W, __half* __restrict__ T, int K, int N)
{
    __shared__ float tile[32][33];
    const int tx = threadIdx.x, ty = threadIdx.y;
    const int nBase = blockIdx.x * 32, kBase = blockIdx.y * 32;
#pragma unroll
    for (int i = 0; i < 4; i++)
        tile[ty + 8 * i][tx] = W[(size_t)(kBase + ty + 8 * i) * N + nBase + tx];
    __syncthreads();
#pragma unroll
    for (int i = 0; i < 4; i++) {
        float v = tile[tx][ty + 8 * i];
        T[(size_t)(nBase + ty + 8 * i) * K + kBase + tx] = __float2half(v);
    }
}

// ---------------------------------------------------------------------------
// Unified single-product fp16 GEMM, 4 CTAs/SM version:
// CTA tile 128x64, 256 threads, 8 warps (4M x 2N), warp tile 32x32.
// 2-stage pipeline (48KB smem), two barriers/iter; 4 CTAs/SM (32 warps/SM)
// cover the ldmatrix->mma gaps cross-CTA.
// OMODE 0: fp16 out, +bias, per-column qscale. OMODE 1: fp32 out, no bias.
// ---------------------------------------------------------------------------
#define G2_STAGE_BYTES 24576                 // A 16KB + B 8KB
#define G2_SMEM_BYTES  (2 * G2_STAGE_BYTES)  // 49152; x4 CTAs = 196608 <= 227KB

template <int OMODE>
__global__ __launch_bounds__(256, 4) void gemm_f16_kernel(
    const __half* __restrict__ A, const __half* __restrict__ B,
    const float* __restrict__ bias, __half* __restrict__ Ch,
    float* __restrict__ Cf, float qsc, int qcols, int M, int N, int K)
{
    extern __shared__ char gsm[];
    const uint32_t sb = smem_u32(gsm);

    const int tid   = threadIdx.x;
    const int wid   = tid >> 5;
    const int lane  = tid & 31;
    const int warpM = wid & 3;          // 0..3 -> 32 rows each
    const int warpN = wid >> 2;         // 0..1 -> 32 cols each
    const int mBase = blockIdx.y * 128;
    const int nBase = blockIdx.x * 64;
    const int nCh   = K >> 6;

    const int aRowOff = lane & 15;
    const int aKOff   = (lane >> 4) << 4;
    const int bRowOff = (lane & 7) + ((lane >> 4) << 3);
    const int bKOff   = ((lane >> 3) & 1) << 4;

    auto swz = [](uint32_t off) { return off ^ ((off >> 3) & 0x70); };

    auto load_chunk = [&](int ci) {
        const int k0 = ci << 6;
        const uint32_t sbase = sb + (uint32_t)(ci & 1) * G2_STAGE_BYTES;
#pragma unroll
        for (int t = 0; t < 6; t++) {
            int idx = tid + t * 256;            // 0..1535
            if (idx < 1024) {                   // A: 128 rows x 8 granules
                int row = idx >> 3;
                int gr  = idx & 7;
                uint32_t off = (uint32_t)(row * 128 + gr * 16);
                uint32_t sw  = off ^ ((off >> 3) & 0x70);
                cp16(sbase + sw, A + (size_t)(mBase + row) * K + k0 + gr * 8);
            } else {                            // B: 64 rows x 8 granules
                int idx2 = idx - 1024;
                int row  = idx2 >> 3;
                int gr   = idx2 & 7;
                uint32_t off = (uint32_t)(row * 128 + gr * 16);
                uint32_t sw  = off ^ ((off >> 3) & 0x70);
                cp16(sbase + 16384 + sw,
                     B + (size_t)(nBase + row) * K + k0 + gr * 8);
            }
        }
        asm volatile("cp.async.commit_group;" ::: "memory");
    };

    float acc[2][4][4];
#pragma unroll
    for (int mt = 0; mt < 2; mt++)
#pragma unroll
        for (int nt = 0; nt < 4; nt++)
#pragma unroll
            for (int i = 0; i < 4; i++) acc[mt][nt][i] = 0.f;

    load_chunk(0);
    load_chunk(1);

    for (int ci = 0; ci < nCh; ci++) {
        if (ci + 1 < nCh)
            asm volatile("cp.async.wait_group 1;" ::: "memory");
        else
            asm volatile("cp.async.wait_group 0;" ::: "memory");
        __syncthreads();

        const uint32_t sbase = sb + (uint32_t)(ci & 1) * G2_STAGE_BYTES;
        const uint32_t aB = sbase;
        const uint32_t bB = sbase + 16384;

#pragma unroll
        for (int ks = 0; ks < 4; ks++) {
            const int kByte = ks * 32;
            uint32_t af[2][4];
#pragma unroll
            for (int mt = 0; mt < 2; mt++) {
                uint32_t off = (uint32_t)((warpM * 32 + mt * 16 + aRowOff) * 128
                                          + kByte + aKOff);
                ldmx4(af[mt], aB + swz(off));
            }
            uint32_t bf[2][4];
#pragma unroll
            for (int p = 0; p < 2; p++) {
                uint32_t off = (uint32_t)((warpN * 32 + p * 16 + bRowOff) * 128
                                          + kByte + bKOff);
                ldmx4(bf[p], bB + swz(off));
            }
#pragma unroll
            for (int mt = 0; mt < 2; mt++)
#pragma unroll
                for (int nt = 0; nt < 4; nt++)
                    mma16816h(acc[mt][nt], af[mt], &bf[nt >> 1][(nt & 1) * 2]);
        }
        __syncthreads();   // all warps done reading buf ci&1
        if (ci + 2 < nCh) load_chunk(ci + 2);   // overwrites buf ci&1
    }

    const int mW = mBase + warpM * 32;
    const int nW = nBase + warpN * 32;
#pragma unroll
    for (int mt = 0; mt < 2; mt++) {
#pragma unroll
        for (int nt = 0; nt < 4; nt++) {
            int r0 = mW + mt * 16 + (lane >> 2);
            int c  = nW + nt * 8 + (lane & 3) * 2;
            if (OMODE == 0) {
                float2 bv = *(const float2*)(bias + c);
                float sc = (c < qcols) ? qsc : 1.f;
                float v0 = (acc[mt][nt][0] + bv.x) * sc;
                float v1 = (acc[mt][nt][1] + bv.y) * sc;
                float v2 = (acc[mt][nt][2] + bv.x) * sc;
                float v3 = (acc[mt][nt][3] + bv.y) * sc;
                __half2 h01 = __floats2half2_rn(v0, v1);
                __half2 h23 = __floats2half2_rn(v2, v3);
                *(uint32_t*)(Ch + (size_t)r0 * N + c)       = *(uint32_t*)&h01;
                *(uint32_t*)(Ch + (size_t)(r0 + 8) * N + c) = *(uint32_t*)&h23;
            } else {
                *(float2*)(Cf + (size_t)r0 * N + c) =
                    make_float2(acc[mt][nt][0], acc[mt][nt][1]);
                *(float2*)(Cf + (size_t)(r0 + 8) * N + c) =
                    make_float2(acc[mt][nt][2], acc[mt][nt][3]);
            }
        }
    }
}

// ---------------------------------------------------------------------------
// Flash attention, fp16 single-product mma (numerically identical to R14/R15).
// BM=64, 128 threads (4 warps), 3 CTAs/SM (register-file capped).
// 2-stage K/V pipeline; Q parked at sb, aliased by stage 1 after the hoist.
// ---------------------------------------------------------------------------
#define FA_SMEM_BYTES (2 * 32768)   // 65536; 3 CTAs/SM -> 192KB

__global__ __launch_bounds__(128, 3) void flash_mma_kernel(
    const __half* __restrict__ qkv, __half* __restrict__ oh)
{
    extern __shared__ char fsm[];
    const uint32_t sb  = smem_u32(fsm);
    const int tid  = threadIdx.x;
    const int wid  = tid >> 5;        // 0..3
    const int lane = tid & 31;
    const int q0 = blockIdx.x * 64;
    const int h  = blockIdx.y;
    const int b  = blockIdx.z;
    const int g  = h >> 2;

    const size_t qrow0 = (size_t)b * SEQ + q0;
    const int qcol = h * HD;
    const int kcol = EMB + g * HD;
    const int vcol = EMB + KVW + g * HD;

#pragma unroll
    for (int t = 0; t < 8; t++) {
        int idx = tid + t * 128;
        int row = idx >> 4;
        int gr  = idx & 15;
        int blk = gr >> 3;
        uint32_t off = (uint32_t)(row * 128 + (gr & 7) * 16);
        uint32_t sw  = off ^ ((off >> 3) & 0x70);
        size_t go = (qrow0 + row) * QKVW + qcol + gr * 8;
        cp16(sb + blk * 8192 + sw, qkv + go);
    }
    asm volatile("cp.async.commit_group;" ::: "memory");

    auto stage_base = [&](int s) -> uint32_t {
        return sb + (uint32_t)(((s + 1) & 1) * 32768);
    };

    auto load_stage = [&](int ci) {
        const uint32_t s0 = stage_base(ci);
        const int kr0 = ci * 64;
#pragma unroll
        for (int t = 0; t < 16; t++) {
            int arr = t >> 3;
            int idx = tid + (t & 7) * 128;
            int row = idx >> 4;
            int gr  = idx & 15;
            int blk = gr >> 3;
            uint32_t off = (uint32_t)(row * 128 + (gr & 7) * 16);
            uint32_t sw  = off ^ ((off >> 3) & 0x70);
            uint32_t dst = s0 + (uint32_t)arr * 16384u + (uint32_t)blk * 8192u + sw;
            int col = (arr == 0) ? kcol : vcol;
            size_t go = (size_t)(b * SEQ + kr0 + row) * QKVW + col + gr * 8;
            cp16(dst, qkv + go);
        }
        asm volatile("cp.async.commit_group;" ::: "memory");
    };

    load_stage(0);

    const int gid = lane >> 2, tig = lane & 3;
    const int qrw = wid * 16;

    const int aRow = lane & 15;
    const int aCol = (lane >> 4) << 4;
    const int bRow = (lane & 7) + ((lane >> 4) << 3);
    const int bCol = ((lane >> 3) & 1) << 4;
    const int vRow = (lane & 7) + (((lane >> 3) & 1) << 3);
    const int vCol = (lane >> 4) << 4;

    asm volatile("cp.async.wait_group 1;" ::: "memory");
    __syncthreads();
    uint32_t qreg[8][4];
#pragma unroll
    for (int ks = 0; ks < 8; ks++) {
        const int blk = ks >> 2;
        const int kb  = (ks & 3) * 32;
        uint32_t offq = (uint32_t)((qrw + aRow) * 128 + kb + aCol);
        uint32_t swq  = offq ^ ((offq >> 3) & 0x70);
        ldmx4(qreg[ks], sb + blk * 8192 + swq);
    }
    __syncthreads();
    load_stage(1);

    float m0 = -1e30f, m1 = -1e30f, l0 = 0.f, l1 = 0.f;
    float o[16][4];
#pragma unroll
    for (int t = 0; t < 16; t++)
#pragma unroll
        for (int i = 0; i < 4; i++) o[t][i] = 0.f;

    const int NIT = SEQ / 64;
    for (int ci = 0; ci < NIT; ci++) {
        if (ci + 1 < NIT)
            asm volatile("cp.async.wait_group 1;" ::: "memory");
        else
            asm volatile("cp.async.wait_group 0;" ::: "memory");
        __syncthreads();

        const uint32_t s0 = stage_base(ci);
        const uint32_t KB = s0, VB = s0 + 16384;

        // ---- S = Q @ K^T (Q from registers) ----
        float s[8][4];
#pragma unroll
        for (int t = 0; t < 8; t++)
#pragma unroll
            for (int i = 0; i < 4; i++) s[t][i] = 0.f;

#pragma unroll
        for (int ks = 0; ks < 8; ks++) {
            const int blk = ks >> 2;
            const int kb  = (ks & 3) * 32;
#pragma unroll
            for (int nb = 0; nb < 4; nb++) {
                uint32_t kf[4];
                uint32_t offk = (uint32_t)((nb * 16 + bRow) * 128 + kb + bCol);
                uint32_t swk  = offk ^ ((offk >> 3) & 0x70);
                ldmx4(kf, KB + blk * 8192 + swk);
                mma16816h(s[2 * nb],     qreg[ks], &kf[0]);
                mma16816h(s[2 * nb + 1], qreg[ks], &kf[2]);
            }
        }

        // ---- online softmax (log2 domain) ----
        float mx0 = -1e30f, mx1 = -1e30f;
#pragma unroll
        for (int t = 0; t < 8; t++) {
            mx0 = fmaxf(mx0, fmaxf(s[t][0], s[t][1]));
            mx1 = fmaxf(mx1, fmaxf(s[t][2], s[t][3]));
        }
        mx0 = fmaxf(mx0, __shfl_xor_sync(0xffffffffu, mx0, 1));
        mx0 = fmaxf(mx0, __shfl_xor_sync(0xffffffffu, mx0, 2));
        mx1 = fmaxf(mx1, __shfl_xor_sync(0xffffffffu, mx1, 1));
        mx1 = fmaxf(mx1, __shfl_xor_sync(0xffffffffu, mx1, 2));

        float mn0 = fmaxf(m0, mx0), mn1 = fmaxf(m1, mx1);
        float a0 = ex2(m0 - mn0), a1 = ex2(m1 - mn1);
        m0 = mn0; m1 = mn1;

        float rs0 = 0.f, rs1 = 0.f;
        uint32_t pa[4][4];
#pragma unroll
        for (int t = 0; t < 8; t++) {
            __half2 h01 = h2exp2(__floats2half2_rn(s[t][0] - mn0, s[t][1] - mn0));
            __half2 h23 = h2exp2(__floats2half2_rn(s[t][2] - mn1, s[t][3] - mn1));
            float2 f01 = __half22float2(h01);
            float2 f23 = __half22float2(h23);
            rs0 += f01.x + f01.y;
            rs1 += f23.x + f23.y;
            int j = t >> 1, sl = (t & 1) * 2;
            pa[j][sl]     = *(uint32_t*)&h01;
            pa[j][sl + 1] = *(uint32_t*)&h23;
        }
        rs0 += __shfl_xor_sync(0xffffffffu, rs0, 1);
        rs0 += __shfl_xor_sync(0xffffffffu, rs0, 2);
        rs1 += __shfl_xor_sync(0xffffffffu, rs1, 1);
        rs1 += __shfl_xor_sync(0xffffffffu, rs1, 2);
        l0 = l0 * a0 + rs0;
        l1 = l1 * a1 + rs1;

        if (a0 != 1.f || a1 != 1.f) {
#pragma unroll
            for (int t = 0; t < 16; t++) {
                o[t][0] *= a0; o[t][1] *= a0;
                o[t][2] *= a1; o[t][3] *= a1;
            }
        }

        // ---- O += P @ V ----
#pragma unroll
        for (int tp = 0; tp < 8; tp++) {
            const int blk = tp >> 2;
            const int cb  = (tp & 3) * 32 + vCol;
#pragma unroll
            for (int j = 0; j < 4; j++) {
                uint32_t vf[4];
                uint32_t offv = (uint32_t)((j * 16 + vRow) * 128 + cb);
                uint32_t swv  = offv ^ ((offv >> 3) & 0x70);
                ldmx4t(vf, VB + blk * 8192 + swv);
                mma16816h(o[2 * tp],     pa[j], &vf[0]);
                mma16816h(o[2 * tp + 1], pa[j], &vf[2]);
            }
        }

        __syncthreads();
        if (ci + 2 < NIT) load_stage(ci + 2);
    }

    float i0 = 1.0f / l0, i1 = 1.0f / l1;
    size_t r0 = (qrow0 + qrw + gid) * EMB + (size_t)h * HD;
    size_t r1 = (qrow0 + qrw + gid + 8) * EMB + (size_t)h * HD;
#pragma unroll
    for (int t = 0; t < 16; t++) {
        int c = t * 8 + tig * 2;
        __half2 ha = __floats2half2_rn(o[t][0] * i0, o[t][1] * i0);
        __half2 hb = __floats2half2_rn(o[t][2] * i1, o[t][3] * i1);
        *(uint32_t*)(oh + r0 + c) = *(uint32_t*)&ha;
        *(uint32_t*)(oh + r1 + c) = *(uint32_t*)&hb;
    }
}

// ---------------------------------------------------------------------------
// kernel_launch
// ---------------------------------------------------------------------------
extern "C" void kernel_launch(void* const* d_in, const int* in_sizes, int n_in,
                              void* d_out, int out_size)
{
    const float* x  = (const float*)d_in[0];
    const float* Wq = (const float*)d_in[1];
    const float* bq = (const float*)d_in[2];
    const float* Wk = (const float*)d_in[3];
    const float* bk = (const float*)d_in[4];
    const float* Wv = (const float*)d_in[5];
    const float* bv = (const float*)d_in[6];
    const float* Wo = (const float*)d_in[7];
    float* out = (float*)d_out;

    __half *pxh, *pqkv, *pwc, *poh, *pwo;
    float* pbias;
    cudaGetSymbolAddress((void**)&pxh,  g_xh);
    cudaGetSymbolAddress((void**)&pqkv, g_qkv);
    cudaGetSymbolAddress((void**)&pwc,  g_wc);
    cudaGetSymbolAddress((void**)&poh,  g_oh);
    cudaGetSymbolAddress((void**)&pwo,  g_wo);
    cudaGetSymbolAddress((void**)&pbias, g_bias);

    cudaFuncSetAttribute(gemm_f16_kernel<0>,
                         cudaFuncAttributeMaxDynamicSharedMemorySize, G2_SMEM_BYTES);
    cudaFuncSetAttribute(gemm_f16_kernel<1>,
                         cudaFuncAttributeMaxDynamicSharedMemorySize, G2_SMEM_BYTES);
    cudaFuncSetAttribute(flash_mma_kernel,
                         cudaFuncAttributeMaxDynamicSharedMemorySize, FA_SMEM_BYTES);

    const int nx = MROWS * EMB;
    // q pre-scale: log2(e) / sqrt(HD)  (softmax runs in log2 domain)
    const float qscale = 0.088388347648318447f * 1.4426950408889634f;

    // 1) x -> fp16
    to_half_kernel<<<nx / (4 * 256), 256>>>(x, pxh, nx);

    // 2) weights: QKV concat transpose (+fused bias concat); Wo -> fp16
    dim3 tb(32, 8);
    transpose_qkv_kernel<<<dim3(QKVW / 32, EMB / 32), tb>>>(
        Wq, Wk, Wv, pwc, bq, bk, bv, pbias);
    transpose_half_kernel<<<dim3(EMB / 32, EMB / 32), tb>>>(Wo, pwo, EMB, EMB);

    // 3) fused QKV projection, single-product fp16 (Q cols pre-scaled)
    gemm_f16_kernel<0><<<dim3(QKVW / 64, MROWS / 128), 256, G2_SMEM_BYTES>>>(
        pxh, pwc, pbias, pqkv, nullptr, qscale, EMB, MROWS, QKVW, EMB);

    // 4) flash attention (fp16, BM=64, 3 CTAs/SM) -> single fp16 output
    flash_mma_kernel<<<dim3(SEQ / 64, HQ, BATCH), 128, FA_SMEM_BYTES>>>(
        pqkv, poh);

    // 5) output projection: single-product fp16 -> fp32
    gemm_f16_kernel<1><<<dim3(EMB / 64, MROWS / 128), 256, G2_SMEM_BYTES>>>(
        poh, pwo, (const float*)nullptr, nullptr, out, 1.0f, 0,
        MROWS, EMB, EMB);
}

// round 17
// speedup vs baseline: 1.0407x; 1.0407x over previous
#include <cuda_runtime.h>
#include <cuda_bf16.h>
#include <cuda_fp16.h>
#include <cstdint>

#define BATCH 2
#define SEQ   2048
#define EMB   2048
#define HQ    16
#define HKV   4
#define HD    128
#define KVW   (HKV * HD)        // 512
#define MROWS (BATCH * SEQ)     // 4096
#define QKVW  (EMB + 2 * KVW)   // 3072

// ---------------------------------------------------------------------------
// PTX helpers — ONLY non-arch-suffixed instructions (compute_103-safe)
// ---------------------------------------------------------------------------
__device__ __forceinline__ uint32_t smem_u32(const void* p) {
    uint32_t a;
    asm("{ .reg .u64 t; cvta.to.shared.u64 t, %1; cvt.u32.u64 %0, t; }"
        : "=r"(a) : "l"(p));
    return a;
}

__device__ __forceinline__ void cp16(uint32_t saddr, const void* gaddr) {
    asm volatile("cp.async.cg.shared.global [%0], [%1], 16;"
                 :: "r"(saddr), "l"(gaddr));
}

__device__ __forceinline__ void ldmx4(uint32_t* r, uint32_t addr) {
    asm volatile("ldmatrix.sync.aligned.m8n8.x4.shared.b16 {%0,%1,%2,%3}, [%4];"
                 : "=r"(r[0]), "=r"(r[1]), "=r"(r[2]), "=r"(r[3]) : "r"(addr));
}

__device__ __forceinline__ void ldmx4t(uint32_t* r, uint32_t addr) {
    asm volatile("ldmatrix.sync.aligned.m8n8.x4.trans.shared.b16 {%0,%1,%2,%3}, [%4];"
                 : "=r"(r[0]), "=r"(r[1]), "=r"(r[2]), "=r"(r[3]) : "r"(addr));
}

// fp16 mma
__device__ __forceinline__ void mma16816h(float* c, const uint32_t* a,
                                          const uint32_t* b) {
    asm volatile(
        "mma.sync.aligned.m16n8k16.row.col.f32.f16.f16.f32 "
        "{%0,%1,%2,%3}, {%4,%5,%6,%7}, {%8,%9}, {%0,%1,%2,%3};"
        : "+f"(c[0]), "+f"(c[1]), "+f"(c[2]), "+f"(c[3])
        : "r"(a[0]), "r"(a[1]), "r"(a[2]), "r"(a[3]), "r"(b[0]), "r"(b[1]));
}

__device__ __forceinline__ float ex2(float x) {
    float y;
    asm("ex2.approx.f32 %0, %1;" : "=f"(y) : "f"(x));
    return y;
}

// ---------------------------------------------------------------------------
// Device scratch (no cudaMalloc allowed)
// ---------------------------------------------------------------------------
__device__ __half g_xh[(size_t)MROWS * EMB];       // x fp16
__device__ __half g_qkv[(size_t)MROWS * QKVW];     // fused q|k|v fp16
__device__ __half g_oh[(size_t)MROWS * EMB];       // attn out fp16
__device__ __half g_wc[(size_t)QKVW * EMB];        // concat Wq|Wk|Wv ^T fp16
__device__ __half g_wo[(size_t)EMB * EMB];         // Wo^T fp16
__device__ float  g_bias[QKVW];                    // concat bq|bk|bv

// ---------------------------------------------------------------------------
// fp32 -> fp16 convert (elementwise)
// ---------------------------------------------------------------------------
__global__ __launch_bounds__(256) void to_half_kernel(
    const float* __restrict__ x, __half* __restrict__ y, int n)
{
    int i = (blockIdx.x * 256 + threadIdx.x) * 4;
    if (i >= n) return;
    float4 v = *(const float4*)(x + i);
    __half2 h0 = __floats2half2_rn(v.x, v.y);
    __half2 h1 = __floats2half2_rn(v.z, v.w);
    uint2 o = make_uint2(*(uint32_t*)&h0, *(uint32_t*)&h1);
    *(uint2*)(y + i) = o;
}

// ---------------------------------------------------------------------------
// Merged transpose of ALL weights in ONE launch:
//   nBase in [0, QKVW)       : Wq|Wk|Wv -> g_wc   (+fused bias concat)
//   nBase in [QKVW, QKVW+EMB): Wo       -> g_wo
// All sources are [EMB, srcN] fp32; outputs are [*, EMB] fp16 (stride EMB).
// ---------------------------------------------------------------------------
__global__ __launch_bounds__(256) void transpose_all_kernel(
    const float* __restrict__ Wq, const float* __restrict__ Wk,
    const float* __restrict__ Wv, const float* __restrict__ Wo,
    __half* __restrict__ Tc, __half* __restrict__ To,
    const float* __restrict__ bq, const float* __restrict__ bk,
    const float* __restrict__ bv, float* __restrict__ biasOut)
{
    __shared__ float tile[32][33];
    const int tx = threadIdx.x, ty = threadIdx.y;
    const int nBase = blockIdx.x * 32;   // 0..QKVW+EMB-32
    const int kBase = blockIdx.y * 32;   // 0..EMB-32

    const float* W;
    const float* bsrc = nullptr;
    __half* T;
    int srcN, ln, outRow;
    if (nBase < EMB) {
        W = Wq; bsrc = bq; srcN = EMB; ln = nBase; T = Tc; outRow = nBase;
    } else if (nBase < EMB + KVW) {
        W = Wk; bsrc = bk; srcN = KVW; ln = nBase - EMB; T = Tc; outRow = nBase;
    } else if (nBase < QKVW) {
        W = Wv; bsrc = bv; srcN = KVW; ln = nBase - EMB - KVW; T = Tc; outRow = nBase;
    } else {
        W = Wo; srcN = EMB; ln = nBase - QKVW; T = To; outRow = nBase - QKVW;
    }

    if (bsrc != nullptr && kBase == 0 && ty == 0)
        biasOut[nBase + tx] = bsrc[ln + tx];

#pragma unroll
    for (int i = 0; i < 4; i++)
        tile[ty + 8 * i][tx] = W[(size_t)(kBase + ty + 8 * i) * srcN + ln + tx];
    __syncthreads();
#pragma unroll
    for (int i = 0; i < 4; i++) {
        float v = tile[tx][ty + 8 * i];
        T[(size_t)(outRow + ty + 8 * i) * EMB + kBase + tx] = __float2half(v);
    }
}

// ---------------------------------------------------------------------------
// Unified single-product fp16 GEMM (R14/R15 config — the measured optimum):
// CTA tile 128x64, 256 threads, 8 warps (4M x 2N), warp tile 32x32.
// Stage = A 16KB + B 8KB = 24KB; 3 stages (72KB), single barrier per iter,
// 3 CTAs/SM (24 warps/SM), regs ~80.
// OMODE 0: fp16 out, +bias, per-column qscale. OMODE 1: fp32 out, no bias.
// ---------------------------------------------------------------------------
#define G2_STAGE_BYTES 24576                 // A 16KB + B 8KB
#define G2_SMEM_BYTES  (3 * G2_STAGE_BYTES)  // 73728; x3 CTAs = 221184 <= 227KB

template <int OMODE>
__global__ __launch_bounds__(256, 3) void gemm_f16_kernel(
    const __half* __restrict__ A, const __half* __restrict__ B,
    const float* __restrict__ bias, __half* __restrict__ Ch,
    float* __restrict__ Cf, float qsc, int qcols, int M, int N, int K)
{
    extern __shared__ char gsm[];
    const uint32_t sb = smem_u32(gsm);

    const int tid   = threadIdx.x;
    const int wid   = tid >> 5;
    const int lane  = tid & 31;
    const int warpM = wid & 3;          // 0..3 -> 32 rows each
    const int warpN = wid >> 2;         // 0..1 -> 32 cols each
    const int mBase = blockIdx.y * 128;
    const int nBase = blockIdx.x * 64;
    const int nCh   = K >> 6;

    const int aRowOff = lane & 15;
    const int aKOff   = (lane >> 4) << 4;
    const int bRowOff = (lane & 7) + ((lane >> 4) << 3);
    const int bKOff   = ((lane >> 3) & 1) << 4;

    auto swz = [](uint32_t off) { return off ^ ((off >> 3) & 0x70); };

    auto load_chunk = [&](int ci) {
        const int k0 = ci << 6;
        const uint32_t sbase = sb + (uint32_t)(ci % 3) * G2_STAGE_BYTES;
#pragma unroll
        for (int t = 0; t < 6; t++) {
            int idx = tid + t * 256;            // 0..1535
            if (idx < 1024) {                   // A: 128 rows x 8 granules
                int row = idx >> 3;
                int gr  = idx & 7;
                uint32_t off = (uint32_t)(row * 128 + gr * 16);
                uint32_t sw  = off ^ ((off >> 3) & 0x70);
                cp16(sbase + sw, A + (size_t)(mBase + row) * K + k0 + gr * 8);
            } else {                            // B: 64 rows x 8 granules
                int idx2 = idx - 1024;
                int row  = idx2 >> 3;
                int gr   = idx2 & 7;
                uint32_t off = (uint32_t)(row * 128 + gr * 16);
                uint32_t sw  = off ^ ((off >> 3) & 0x70);
                cp16(sbase + 16384 + sw,
                     B + (size_t)(nBase + row) * K + k0 + gr * 8);
            }
        }
        asm volatile("cp.async.commit_group;" ::: "memory");
    };

    float acc[2][4][4];
#pragma unroll
    for (int mt = 0; mt < 2; mt++)
#pragma unroll
        for (int nt = 0; nt < 4; nt++)
#pragma unroll
            for (int i = 0; i < 4; i++) acc[mt][nt][i] = 0.f;

    load_chunk(0);
    load_chunk(1);

    for (int ci = 0; ci < nCh; ci++) {
        if (ci + 1 < nCh)
            asm volatile("cp.async.wait_group 1;" ::: "memory");
        else
            asm volatile("cp.async.wait_group 0;" ::: "memory");
        __syncthreads();   // also retires reads of buf (ci+2)%3 from iter ci-1

        if (ci + 2 < nCh) load_chunk(ci + 2);

        const uint32_t sbase = sb + (uint32_t)(ci % 3) * G2_STAGE_BYTES;
        const uint32_t aB = sbase;
        const uint32_t bB = sbase + 16384;

#pragma unroll
        for (int ks = 0; ks < 4; ks++) {
            const int kByte = ks * 32;
            uint32_t af[2][4];
#pragma unroll
            for (int mt = 0; mt < 2; mt++) {
                uint32_t off = (uint32_t)((warpM * 32 + mt * 16 + aRowOff) * 128
                                          + kByte + aKOff);
                ldmx4(af[mt], aB + swz(off));
            }
            uint32_t bf[2][4];
#pragma unroll
            for (int p = 0; p < 2; p++) {
                uint32_t off = (uint32_t)((warpN * 32 + p * 16 + bRowOff) * 128
                                          + kByte + bKOff);
                ldmx4(bf[p], bB + swz(off));
            }
#pragma unroll
            for (int mt = 0; mt < 2; mt++)
#pragma unroll
                for (int nt = 0; nt < 4; nt++)
                    mma16816h(acc[mt][nt], af[mt], &bf[nt >> 1][(nt & 1) * 2]);
        }
        // no trailing sync — next iteration's barrier covers it
    }

    const int mW = mBase + warpM * 32;
    const int nW = nBase + warpN * 32;
#pragma unroll
    for (int mt = 0; mt < 2; mt++) {
#pragma unroll
        for (int nt = 0; nt < 4; nt++) {
            int r0 = mW + mt * 16 + (lane >> 2);
            int c  = nW + nt * 8 + (lane & 3) * 2;
            if (OMODE == 0) {
                float2 bv = *(const float2*)(bias + c);
                float sc = (c < qcols) ? qsc : 1.f;
                float v0 = (acc[mt][nt][0] + bv.x) * sc;
                float v1 = (acc[mt][nt][1] + bv.y) * sc;
                float v2 = (acc[mt][nt][2] + bv.x) * sc;
                float v3 = (acc[mt][nt][3] + bv.y) * sc;
                __half2 h01 = __floats2half2_rn(v0, v1);
                __half2 h23 = __floats2half2_rn(v2, v3);
                *(uint32_t*)(Ch + (size_t)r0 * N + c)       = *(uint32_t*)&h01;
                *(uint32_t*)(Ch + (size_t)(r0 + 8) * N + c) = *(uint32_t*)&h23;
            } else {
                *(float2*)(Cf + (size_t)r0 * N + c) =
                    make_float2(acc[mt][nt][0], acc[mt][nt][1]);
                *(float2*)(Cf + (size_t)(r0 + 8) * N + c) =
                    make_float2(acc[mt][nt][2], acc[mt][nt][3]);
            }
        }
    }
}

// ---------------------------------------------------------------------------
// Flash attention, fp16 single-product mma (identical to R14/R15).
// BM=64, 128 threads (4 warps), 3 CTAs/SM. 2-stage K/V pipeline; Q parked
// at sb, aliased by stage 1 after the register hoist. log2-domain softmax.
// ---------------------------------------------------------------------------
#define FA_SMEM_BYTES (2 * 32768)   // 65536; 3 CTAs/SM -> 192KB

__global__ __launch_bounds__(128, 3) void flash_mma_kernel(
    const __half* __restrict__ qkv, __half* __restrict__ oh)
{
    extern __shared__ char fsm[];
    const uint32_t sb  = smem_u32(fsm);
    const int tid  = threadIdx.x;
    const int wid  = tid >> 5;        // 0..3
    const int lane = tid & 31;
    const int q0 = blockIdx.x * 64;
    const int h  = blockIdx.y;
    const int b  = blockIdx.z;
    const int g  = h >> 2;

    const size_t qrow0 = (size_t)b * SEQ + q0;
    const int qcol = h * HD;
    const int kcol = EMB + g * HD;
    const int vcol = EMB + KVW + g * HD;

#pragma unroll
    for (int t = 0; t < 8; t++) {
        int idx = tid + t * 128;
        int row = idx >> 4;
        int gr  = idx & 15;
        int blk = gr >> 3;
        uint32_t off = (uint32_t)(row * 128 + (gr & 7) * 16);
        uint32_t sw  = off ^ ((off >> 3) & 0x70);
        size_t go = (qrow0 + row) * QKVW + qcol + gr * 8;
        cp16(sb + blk * 8192 + sw, qkv + go);
    }
    asm volatile("cp.async.commit_group;" ::: "memory");

    auto stage_base = [&](int s) -> uint32_t {
        return sb + (uint32_t)(((s + 1) & 1) * 32768);
    };

    auto load_stage = [&](int ci) {
        const uint32_t s0 = stage_base(ci);
        const int kr0 = ci * 64;
#pragma unroll
        for (int t = 0; t < 16; t++) {
            int arr = t >> 3;
            int idx = tid + (t & 7) * 128;
            int row = idx >> 4;
            int gr  = idx & 15;
            int blk = gr >> 3;
            uint32_t off = (uint32_t)(row * 128 + (gr & 7) * 16);
            uint32_t sw  = off ^ ((off >> 3) & 0x70);
            uint32_t dst = s0 + (uint32_t)arr * 16384u + (uint32_t)blk * 8192u + sw;
            int col = (arr == 0) ? kcol : vcol;
            size_t go = (size_t)(b * SEQ + kr0 + row) * QKVW + col + gr * 8;
            cp16(dst, qkv + go);
        }
        asm volatile("cp.async.commit_group;" ::: "memory");
    };

    load_stage(0);

    const int gid = lane >> 2, tig = lane & 3;
    const int qrw = wid * 16;

    const int aRow = lane & 15;
    const int aCol = (lane >> 4) << 4;
    const int bRow = (lane & 7) + ((lane >> 4) << 3);
    const int bCol = ((lane >> 3) & 1) << 4;
    const int vRow = (lane & 7) + (((lane >> 3) & 1) << 3);
    const int vCol = (lane >> 4) << 4;

    asm volatile("cp.async.wait_group 1;" ::: "memory");
    __syncthreads();
    uint32_t qreg[8][4];
#pragma unroll
    for (int ks = 0; ks < 8; ks++) {
        const int blk = ks >> 2;
        const int kb  = (ks & 3) * 32;
        uint32_t offq = (uint32_t)((qrw + aRow) * 128 + kb + aCol);
        uint32_t swq  = offq ^ ((offq >> 3) & 0x70);
        ldmx4(qreg[ks], sb + blk * 8192 + swq);
    }
    __syncthreads();
    load_stage(1);

    float m0 = -1e30f, m1 = -1e30f, l0 = 0.f, l1 = 0.f;
    float o[16][4];
#pragma unroll
    for (int t = 0; t < 16; t++)
#pragma unroll
        for (int i = 0; i < 4; i++) o[t][i] = 0.f;

    const int NIT = SEQ / 64;
    for (int ci = 0; ci < NIT; ci++) {
        if (ci + 1 < NIT)
            asm volatile("cp.async.wait_group 1;" ::: "memory");
        else
            asm volatile("cp.async.wait_group 0;" ::: "memory");
        __syncthreads();

        const uint32_t s0 = stage_base(ci);
        const uint32_t KB = s0, VB = s0 + 16384;

        // ---- S = Q @ K^T (Q from registers) ----
        float s[8][4];
#pragma unroll
        for (int t = 0; t < 8; t++)
#pragma unroll
            for (int i = 0; i < 4; i++) s[t][i] = 0.f;

#pragma unroll
        for (int ks = 0; ks < 8; ks++) {
            const int blk = ks >> 2;
            const int kb  = (ks & 3) * 32;
#pragma unroll
            for (int nb = 0; nb < 4; nb++) {
                uint32_t kf[4];
                uint32_t offk = (uint32_t)((nb * 16 + bRow) * 128 + kb + bCol);
                uint32_t swk  = offk ^ ((offk >> 3) & 0x70);
                ldmx4(kf, KB + blk * 8192 + swk);
                mma16816h(s[2 * nb],     qreg[ks], &kf[0]);
                mma16816h(s[2 * nb + 1], qreg[ks], &kf[2]);
            }
        }

        // ---- online softmax (log2 domain) ----
        float mx0 = -1e30f, mx1 = -1e30f;
#pragma unroll
        for (int t = 0; t < 8; t++) {
            mx0 = fmaxf(mx0, fmaxf(s[t][0], s[t][1]));
            mx1 = fmaxf(mx1, fmaxf(s[t][2], s[t][3]));
        }
        mx0 = fmaxf(mx0, __shfl_xor_sync(0xffffffffu, mx0, 1));
        mx0 = fmaxf(mx0, __shfl_xor_sync(0xffffffffu, mx0, 2));
        mx1 = fmaxf(mx1, __shfl_xor_sync(0xffffffffu, mx1, 1));
        mx1 = fmaxf(mx1, __shfl_xor_sync(0xffffffffu, mx1, 2));

        float mn0 = fmaxf(m0, mx0), mn1 = fmaxf(m1, mx1);
        float a0 = ex2(m0 - mn0), a1 = ex2(m1 - mn1);
        m0 = mn0; m1 = mn1;

        float rs0 = 0.f, rs1 = 0.f;
        uint32_t pa[4][4];
#pragma unroll
        for (int t = 0; t < 8; t++) {
            __half2 h01 = h2exp2(__floats2half2_rn(s[t][0] - mn0, s[t][1] - mn0));
            __half2 h23 = h2exp2(__floats2half2_rn(s[t][2] - mn1, s[t][3] - mn1));
            float2 f01 = __half22float2(h01);
            float2 f23 = __half22float2(h23);
            rs0 += f01.x + f01.y;
            rs1 += f23.x + f23.y;
            int j = t >> 1, sl = (t & 1) * 2;
            pa[j][sl]     = *(uint32_t*)&h01;
            pa[j][sl + 1] = *(uint32_t*)&h23;
        }
        rs0 += __shfl_xor_sync(0xffffffffu, rs0, 1);
        rs0 += __shfl_xor_sync(0xffffffffu, rs0, 2);
        rs1 += __shfl_xor_sync(0xffffffffu, rs1, 1);
        rs1 += __shfl_xor_sync(0xffffffffu, rs1, 2);
        l0 = l0 * a0 + rs0;
        l1 = l1 * a1 + rs1;

        if (a0 != 1.f || a1 != 1.f) {
#pragma unroll
            for (int t = 0; t < 16; t++) {
                o[t][0] *= a0; o[t][1] *= a0;
                o[t][2] *= a1; o[t][3] *= a1;
            }
        }

        // ---- O += P @ V ----
#pragma unroll
        for (int tp = 0; tp < 8; tp++) {
            const int blk = tp >> 2;
            const int cb  = (tp & 3) * 32 + vCol;
#pragma unroll
            for (int j = 0; j < 4; j++) {
                uint32_t vf[4];
                uint32_t offv = (uint32_t)((j * 16 + vRow) * 128 + cb);
                uint32_t swv  = offv ^ ((offv >> 3) & 0x70);
                ldmx4t(vf, VB + blk * 8192 + swv);
                mma16816h(o[2 * tp],     pa[j], &vf[0]);
                mma16816h(o[2 * tp + 1], pa[j], &vf[2]);
            }
        }

        __syncthreads();
        if (ci + 2 < NIT) load_stage(ci + 2);
    }

    float i0 = 1.0f / l0, i1 = 1.0f / l1;
    size_t r0 = (qrow0 + qrw + gid) * EMB + (size_t)h * HD;
    size_t r1 = (qrow0 + qrw + gid + 8) * EMB + (size_t)h * HD;
#pragma unroll
    for (int t = 0; t < 16; t++) {
        int c = t * 8 + tig * 2;
        __half2 ha = __floats2half2_rn(o[t][0] * i0, o[t][1] * i0);
        __half2 hb = __floats2half2_rn(o[t][2] * i1, o[t][3] * i1);
        *(uint32_t*)(oh + r0 + c) = *(uint32_t*)&ha;
        *(uint32_t*)(oh + r1 + c) = *(uint32_t*)&hb;
    }
}

// ---------------------------------------------------------------------------
// kernel_launch
// ---------------------------------------------------------------------------
extern "C" void kernel_launch(void* const* d_in, const int* in_sizes, int n_in,
                              void* d_out, int out_size)
{
    const float* x  = (const float*)d_in[0];
    const float* Wq = (const float*)d_in[1];
    const float* bq = (const float*)d_in[2];
    const float* Wk = (const float*)d_in[3];
    const float* bk = (const float*)d_in[4];
    const float* Wv = (const float*)d_in[5];
    const float* bv = (const float*)d_in[6];
    const float* Wo = (const float*)d_in[7];
    float* out = (float*)d_out;

    __half *pxh, *pqkv, *pwc, *poh, *pwo;
    float* pbias;
    cudaGetSymbolAddress((void**)&pxh,  g_xh);
    cudaGetSymbolAddress((void**)&pqkv, g_qkv);
    cudaGetSymbolAddress((void**)&pwc,  g_wc);
    cudaGetSymbolAddress((void**)&poh,  g_oh);
    cudaGetSymbolAddress((void**)&pwo,  g_wo);
    cudaGetSymbolAddress((void**)&pbias, g_bias);

    cudaFuncSetAttribute(gemm_f16_kernel<0>,
                         cudaFuncAttributeMaxDynamicSharedMemorySize, G2_SMEM_BYTES);
    cudaFuncSetAttribute(gemm_f16_kernel<1>,
                         cudaFuncAttributeMaxDynamicSharedMemorySize, G2_SMEM_BYTES);
    cudaFuncSetAttribute(flash_mma_kernel,
                         cudaFuncAttributeMaxDynamicSharedMemorySize, FA_SMEM_BYTES);

    const int nx = MROWS * EMB;
    // q pre-scale: log2(e) / sqrt(HD)  (softmax runs in log2 domain)
    const float qscale = 0.088388347648318447f * 1.4426950408889634f;

    // 1) x -> fp16
    to_half_kernel<<<nx / (4 * 256), 256>>>(x, pxh, nx);

    // 2) ALL weight transposes + bias concat in one launch
    dim3 tb(32, 8);
    transpose_all_kernel<<<dim3((QKVW + EMB) / 32, EMB / 32), tb>>>(
        Wq, Wk, Wv, Wo, pwc, pwo, bq, bk, bv, pbias);

    // 3) fused QKV projection, single-product fp16 (Q cols pre-scaled)
    gemm_f16_kernel<0><<<dim3(QKVW / 64, MROWS / 128), 256, G2_SMEM_BYTES>>>(
        pxh, pwc, pbias, pqkv, nullptr, qscale, EMB, MROWS, QKVW, EMB);

    // 4) flash attention (fp16, BM=64, 3 CTAs/SM) -> single fp16 output
    flash_mma_kernel<<<dim3(SEQ / 64, HQ, BATCH), 128, FA_SMEM_BYTES>>>(
        pqkv, poh);

    // 5) output projection: single-product fp16 -> fp32
    gemm_f16_kernel<1><<<dim3(EMB / 64, MROWS / 128), 256, G2_SMEM_BYTES>>>(
        poh, pwo, (const float*)nullptr, nullptr, out, 1.0f, 0,
        MROWS, EMB, EMB);
}